// round 3
// baseline (speedup 1.0000x reference)
#include <cuda_runtime.h>
#include <math.h>

#define DINL __device__ __forceinline__

namespace {
constexpr int NS  = 2;      // 0 = factual, 1 = counterfactual
constexpr int NB  = 4;      // batch
constexpr int LKV = 1024;
constexpr int LL  = 2048;   // total seq len per block
constexpr int DMO = 512;    // d_model
constexpr int DPJ = 2192;   // d_in_proj
constexpr int DI  = 1024;   // d_inner
constexpr int DSZ = 64;     // d_state
constexpr int NH  = 16;
constexpr int HD  = 64;
constexpr int CC  = 1152;   // conv channels = DI + 2*DSZ
constexpr int CH  = 128;    // scan chunk length
constexpr int NC  = LL / CH;  // 16 chunks
constexpr int TS  = 8;      // time staging in scan kernels
}

// ---------------- scratch (device globals; no allocation) ----------------
__device__ float g_U  [(size_t)NS*NB*LL*DMO];          // rmsnorm'ed inputs
__device__ float g_Z  [(size_t)NS*NB*LL*DPJ];          // in_proj output
__device__ float g_xbc[(size_t)NS*NB*LL*CC];           // conv+silu output
__device__ float g_dt [(size_t)NS*NB*LL*NH];
__device__ float g_dA [(size_t)NS*NB*LL*NH];
__device__ float g_y  [(size_t)NS*NB*LL*DI];           // scan y -> gated/normed in place
__device__ float g_fs [(size_t)NS*NB*LL*DMO];          // per-block output (pre-final-proj)
__device__ float g_hloc  [(size_t)NS*NB*NH*NC*HD*DSZ]; // chunk-local end states
__device__ float g_hstart[(size_t)NS*NB*NH*NC*HD*DSZ]; // chunk start states
__device__ float g_P  [(size_t)NS*NB*NH*NC];           // per-chunk decay product

DINL float siluf(float x) { return x / (1.f + expf(-x)); }

// ---------------- K1: build normalized input sequences -------------------
__global__ __launch_bounds__(128) void k_build_u(
    const float* __restrict__ q, const float* __restrict__ kv,
    const float* __restrict__ fw, const float* __restrict__ cw)
{
    int t = blockIdx.x, b = blockIdx.y, s = blockIdx.z;
    const float* src;
    if (t < LKV) {
        int tsrc = (s == 0) ? t : (LKV - 1 - t);   // counterfactual flips kv
        src = kv + ((size_t)b*LKV + tsrc)*DMO;
    } else {
        src = q + ((size_t)b*LKV + (t - LKV))*DMO;
    }
    const float* w = (s == 0) ? fw : cw;
    int tid = threadIdx.x;
    float4 v = ((const float4*)src)[tid];
    float ss = v.x*v.x + v.y*v.y + v.z*v.z + v.w*v.w;
    __shared__ float red[4];
    #pragma unroll
    for (int o = 16; o; o >>= 1) ss += __shfl_xor_sync(~0u, ss, o);
    if ((tid & 31) == 0) red[tid >> 5] = ss;
    __syncthreads();
    float tot = red[0] + red[1] + red[2] + red[3];
    float sc = rsqrtf(tot / (float)DMO + 1e-5f);
    float4 w4 = ((const float4*)w)[tid];
    float4 o4 = make_float4(v.x*sc*w4.x, v.y*sc*w4.y, v.z*sc*w4.z, v.w*sc*w4.w);
    ((float4*)(g_U + ((size_t)(s*NB + b)*LL + t)*DMO))[tid] = o4;
}

// ---- SGEMM (fp32, 128x128x16, 8x8/thread, reg-prefetch + smem ping-pong) -
// which: 0 => A=g_U,  C=g_Z   (per-s slices)
//        1 => A=g_y,  C=g_fs  (per-s slices)
//        2 => A=g_fs(s=0) row-remapped, C=Cext (+bias)
__global__ __launch_bounds__(256) void k_sgemm(
    const float* __restrict__ B0, const float* __restrict__ B1,
    const float* __restrict__ bias, float* __restrict__ Cext,
    int which, int M, int N, int K)
{
    constexpr int BMt = 128, BNt = 128, BKt = 16, TM = 8, TN = 8;
    int s = blockIdx.z;
    const float* Ap; float* Cp; int remapA = 0;
    if (which == 0) {
        Ap = g_U + (size_t)s*NB*LL*DMO;  Cp = g_Z + (size_t)s*NB*LL*DPJ;
    } else if (which == 1) {
        Ap = g_y + (size_t)s*NB*LL*DI;   Cp = g_fs + (size_t)s*NB*LL*DMO;
    } else {
        Ap = g_fs; Cp = Cext; remapA = 1;
    }
    const float* Bp = s ? B1 : B0;

    __shared__ float As[2][BKt][BMt + 4];
    __shared__ float Bs[2][BKt][BNt];

    int tid  = threadIdx.x;
    int brow = blockIdx.y * BMt;
    int bcol = blockIdx.x * BNt;
    int tx = tid & 15, ty = tid >> 4;

    float acc[TM][TN];
    #pragma unroll
    for (int i = 0; i < TM; i++)
        #pragma unroll
        for (int j = 0; j < TN; j++) acc[i][j] = 0.f;

    int aRow = tid >> 2;          // 0..63
    int aCol = (tid & 3) << 2;    // 0,4,8,12
    int bRow = tid >> 5;          // 0..7
    int bCol = (tid & 31) << 2;   // 0..124

    // precompute global row/col indices (A-row remap for 'which==2')
    int growA[2];
    #pragma unroll
    for (int r = 0; r < 2; r++) {
        int gr = brow + aRow + r*64;
        if (remapA) gr = ((gr >> 10) << 11) + 1024 + (gr & 1023);
        growA[r] = gr;
    }
    int gcolB = bcol + bCol;
    bool bOK  = gcolB < N;

    // ---- prefetch tile 0 into registers, stage into buffer 0 ----
    float4 va[2], vb[2];
    #pragma unroll
    for (int r = 0; r < 2; r++)
        va[r] = *(const float4*)(Ap + (size_t)growA[r]*K + aCol);
    #pragma unroll
    for (int r = 0; r < 2; r++)
        vb[r] = bOK ? *(const float4*)(Bp + (size_t)(bRow + r*8)*N + gcolB)
                    : make_float4(0.f, 0.f, 0.f, 0.f);
    #pragma unroll
    for (int r = 0; r < 2; r++) {
        int row = aRow + r*64;
        As[0][aCol+0][row] = va[r].x; As[0][aCol+1][row] = va[r].y;
        As[0][aCol+2][row] = va[r].z; As[0][aCol+3][row] = va[r].w;
    }
    #pragma unroll
    for (int r = 0; r < 2; r++)
        *(float4*)&Bs[0][bRow + r*8][bCol] = vb[r];
    __syncthreads();

    int buf = 0;
    for (int k0 = 0; k0 < K; k0 += BKt) {
        int kn = k0 + BKt;
        bool more = kn < K;

        // ---- issue prefetch of next tile (overlaps with FFMA loop) ----
        if (more) {
            #pragma unroll
            for (int r = 0; r < 2; r++)
                va[r] = *(const float4*)(Ap + (size_t)growA[r]*K + kn + aCol);
            #pragma unroll
            for (int r = 0; r < 2; r++)
                vb[r] = bOK ? *(const float4*)(Bp + (size_t)(kn + bRow + r*8)*N + gcolB)
                            : make_float4(0.f, 0.f, 0.f, 0.f);
        }

        // ---- FFMA over current tile ----
        #pragma unroll
        for (int kk = 0; kk < BKt; kk++) {
            float a[TM], bb[TN];
            #pragma unroll
            for (int i = 0; i < TM; i += 4) {
                float4 t4 = *(const float4*)&As[buf][kk][ty*TM + i];
                a[i] = t4.x; a[i+1] = t4.y; a[i+2] = t4.z; a[i+3] = t4.w;
            }
            #pragma unroll
            for (int j = 0; j < TN; j += 4) {
                float4 t4 = *(const float4*)&Bs[buf][kk][tx*TN + j];
                bb[j] = t4.x; bb[j+1] = t4.y; bb[j+2] = t4.z; bb[j+3] = t4.w;
            }
            #pragma unroll
            for (int i = 0; i < TM; i++)
                #pragma unroll
                for (int j = 0; j < TN; j++)
                    acc[i][j] += a[i] * bb[j];
        }

        // ---- commit prefetched tile into the other buffer; single barrier ----
        if (more) {
            int nb = buf ^ 1;
            #pragma unroll
            for (int r = 0; r < 2; r++) {
                int row = aRow + r*64;
                As[nb][aCol+0][row] = va[r].x; As[nb][aCol+1][row] = va[r].y;
                As[nb][aCol+2][row] = va[r].z; As[nb][aCol+3][row] = va[r].w;
            }
            #pragma unroll
            for (int r = 0; r < 2; r++)
                *(float4*)&Bs[nb][bRow + r*8][bCol] = vb[r];
            __syncthreads();
            buf = nb;
        }
    }

    #pragma unroll
    for (int i = 0; i < TM; i++) {
        int gr = brow + ty*TM + i;
        #pragma unroll
        for (int j4 = 0; j4 < TN; j4 += 4) {
            int gc = bcol + tx*TN + j4;
            if (gc < N) {
                float4 o = make_float4(acc[i][j4], acc[i][j4+1], acc[i][j4+2], acc[i][j4+3]);
                if (bias) {
                    float4 b4 = *(const float4*)(bias + gc);
                    o.x += b4.x; o.y += b4.y; o.z += b4.z; o.w += b4.w;
                }
                *(float4*)(Cp + (size_t)gr*N + gc) = o;
            }
        }
    }
}

// ---------------- K3: causal dwconv + silu + dt/dA ------------------------
__global__ __launch_bounds__(128) void k_conv(
    const float* __restrict__ cw0, const float* __restrict__ cw1,
    const float* __restrict__ cb0, const float* __restrict__ cb1,
    const float* __restrict__ db0, const float* __restrict__ db1,
    const float* __restrict__ al0, const float* __restrict__ al1)
{
    int t = blockIdx.x, b = blockIdx.y, s = blockIdx.z;
    const float* cw = s ? cw1 : cw0;
    const float* cb = s ? cb1 : cb0;
    const float* db = s ? db1 : db0;
    const float* al = s ? al1 : al0;
    size_t row = (size_t)(s*NB + b)*LL + t;

    #pragma unroll
    for (int it = 0; it < CC/128; it++) {
        int c = threadIdx.x + it*128;
        float acc = cb[c];
        #pragma unroll
        for (int k = 0; k < 4; k++) {
            int tt = t - 3 + k;
            if (tt >= 0)
                acc += g_Z[(row + (size_t)(tt - t))*DPJ + DI + c] * cw[c*4 + k];
        }
        g_xbc[row*CC + c] = siluf(acc);
    }
    if (threadIdx.x < NH) {
        int h = threadIdx.x;
        float v = g_Z[row*DPJ + 2*DI + 2*DSZ + h] + db[h];
        float dtv = (v > 20.f) ? v : log1pf(expf(v));
        g_dt[row*NH + h] = dtv;
        g_dA[row*NH + h] = expf(-expf(al[h]) * dtv);
    }
}

// ---------------- K4: intra-chunk scan (pass A) ---------------------------
__global__ __launch_bounds__(64) void k_scanA()
{
    int chunk = blockIdx.x;
    int b = blockIdx.y >> 4, h = blockIdx.y & 15;
    int s = blockIdx.z;
    int p = threadIdx.x;
    __shared__ float sB[TS][DSZ], sC[TS][DSZ], sX[TS][DSZ];
    __shared__ float sdA[TS], sdt[TS];

    float4 hreg[16];
    #pragma unroll
    for (int i = 0; i < 16; i++) hreg[i] = make_float4(0.f, 0.f, 0.f, 0.f);
    float Pprod = 1.f;

    size_t rowbase = (size_t)(s*NB + b)*LL + (size_t)chunk*CH;
    for (int t0 = 0; t0 < CH; t0 += TS) {
        __syncthreads();
        #pragma unroll
        for (int tt = 0; tt < TS; tt++) {
            const float* xb = g_xbc + (rowbase + t0 + tt)*CC;
            sB[tt][p] = xb[DI + p];
            sC[tt][p] = xb[DI + DSZ + p];
            sX[tt][p] = xb[h*HD + p];
        }
        if (p < TS) {
            size_t r = rowbase + t0 + p;
            sdA[p] = g_dA[r*NH + h];
            sdt[p] = g_dt[r*NH + h];
        }
        __syncthreads();
        #pragma unroll
        for (int tt = 0; tt < TS; tt++) {
            float dAt = sdA[tt];
            float scv = sdt[tt] * sX[tt][p];
            float y = 0.f;
            #pragma unroll
            for (int n4 = 0; n4 < 16; n4++) {
                float4 b4 = *(const float4*)&sB[tt][n4*4];
                float4 c4 = *(const float4*)&sC[tt][n4*4];
                hreg[n4].x = hreg[n4].x*dAt + scv*b4.x;  y += hreg[n4].x*c4.x;
                hreg[n4].y = hreg[n4].y*dAt + scv*b4.y;  y += hreg[n4].y*c4.y;
                hreg[n4].z = hreg[n4].z*dAt + scv*b4.z;  y += hreg[n4].z*c4.z;
                hreg[n4].w = hreg[n4].w*dAt + scv*b4.w;  y += hreg[n4].w*c4.w;
            }
            Pprod *= dAt;
            g_y[(rowbase + t0 + tt)*DI + h*HD + p] = y;
        }
    }
    size_t hidx = ((((size_t)(s*NB + b)*NH + h)*NC + chunk)*HD + p)*DSZ;
    #pragma unroll
    for (int n4 = 0; n4 < 16; n4++)
        *(float4*)(g_hloc + hidx + n4*4) = hreg[n4];
    if (p == 0) g_P[((size_t)(s*NB + b)*NH + h)*NC + chunk] = Pprod;
}

// ---------------- K5: inter-chunk state combine (pass B) ------------------
__global__ __launch_bounds__(256) void k_stateB()
{
    size_t idx = (size_t)blockIdx.x*256 + threadIdx.x; // over (sbh, p*n): 128*4096
    size_t sbh = idx >> 12;
    size_t pn  = idx & 4095;
    size_t base = sbh*(size_t)NC*4096 + pn;
    const float* Pv = g_P + sbh*NC;
    float hs = 0.f;
    #pragma unroll
    for (int c = 0; c < NC; c++) {
        g_hstart[base + (size_t)c*4096] = hs;
        hs = hs * Pv[c] + g_hloc[base + (size_t)c*4096];
    }
}

// ---------------- K6: inter-chunk correction + D*x (pass C) ---------------
__global__ __launch_bounds__(64) void k_scanC(
    const float* __restrict__ D0, const float* __restrict__ D1)
{
    int chunk = blockIdx.x;
    int b = blockIdx.y >> 4, h = blockIdx.y & 15;
    int s = blockIdx.z;
    int p = threadIdx.x;
    const float* Dv = s ? D1 : D0;
    float Dh = Dv[h];
    __shared__ float sC[TS][DSZ], sX[TS][DSZ];
    __shared__ float sdA[TS];

    float4 hs[16];
    size_t hidx = ((((size_t)(s*NB + b)*NH + h)*NC + chunk)*HD + p)*DSZ;
    #pragma unroll
    for (int n4 = 0; n4 < 16; n4++)
        hs[n4] = *(const float4*)(g_hstart + hidx + n4*4);

    float cum = 1.f;
    size_t rowbase = (size_t)(s*NB + b)*LL + (size_t)chunk*CH;
    for (int t0 = 0; t0 < CH; t0 += TS) {
        __syncthreads();
        #pragma unroll
        for (int tt = 0; tt < TS; tt++) {
            const float* xb = g_xbc + (rowbase + t0 + tt)*CC;
            sC[tt][p] = xb[DI + DSZ + p];
            sX[tt][p] = xb[h*HD + p];
        }
        if (p < TS) sdA[p] = g_dA[(rowbase + t0 + p)*NH + h];
        __syncthreads();
        #pragma unroll
        for (int tt = 0; tt < TS; tt++) {
            cum *= sdA[tt];
            float dot = 0.f;
            #pragma unroll
            for (int n4 = 0; n4 < 16; n4++) {
                float4 c4 = *(const float4*)&sC[tt][n4*4];
                dot += hs[n4].x*c4.x + hs[n4].y*c4.y + hs[n4].z*c4.z + hs[n4].w*c4.w;
            }
            size_t yi = (rowbase + t0 + tt)*DI + h*HD + p;
            g_y[yi] = g_y[yi] + cum*dot + Dh*sX[tt][p];
        }
    }
}

// ---------------- K7: gate (y * silu(z)) + rmsnorm, in place --------------
__global__ __launch_bounds__(256) void k_gatenorm(
    const float* __restrict__ nw0, const float* __restrict__ nw1)
{
    int t = blockIdx.x, b = blockIdx.y, s = blockIdx.z;
    const float* nw = s ? nw1 : nw0;
    size_t row = (size_t)(s*NB + b)*LL + t;
    int tid = threadIdx.x;
    float4 y4 = ((const float4*)(g_y + row*DI))[tid];
    float4 z4 = ((const float4*)(g_Z + row*DPJ))[tid];
    z4.x = siluf(z4.x); z4.y = siluf(z4.y); z4.z = siluf(z4.z); z4.w = siluf(z4.w);
    float4 yz = make_float4(y4.x*z4.x, y4.y*z4.y, y4.z*z4.z, y4.w*z4.w);
    float ss = yz.x*yz.x + yz.y*yz.y + yz.z*yz.z + yz.w*yz.w;
    __shared__ float red[8];
    #pragma unroll
    for (int o = 16; o; o >>= 1) ss += __shfl_xor_sync(~0u, ss, o);
    if ((tid & 31) == 0) red[tid >> 5] = ss;
    __syncthreads();
    float tot = 0.f;
    #pragma unroll
    for (int i = 0; i < 8; i++) tot += red[i];
    float sc = rsqrtf(tot / (float)DI + 1e-5f);
    float4 w4 = ((const float4*)nw)[tid];
    ((float4*)(g_y + row*DI))[tid] =
        make_float4(yz.x*sc*w4.x, yz.y*sc*w4.y, yz.z*sc*w4.z, yz.w*sc*w4.w);
}

// ---------------- K9: copy counterfactual tail to output ------------------
__global__ __launch_bounds__(256) void k_copycf(float* __restrict__ out)
{
    size_t i = (size_t)blockIdx.x*256 + threadIdx.x;   // float4 idx over 4096*512/4
    size_t r  = i >> 7;          // 0..4095
    size_t c4 = i & 127;
    size_t srcrow = ((r >> 10) << 11) + 1024 + (r & 1023);
    float4 v = ((const float4*)(g_fs + (size_t)NB*LL*DMO + srcrow*DMO))[c4];
    ((float4*)(out + (size_t)4096*512))[i] = v;
}

// ---------------- launch ---------------------------------------------------
extern "C" void kernel_launch(void* const* d_in, const int* in_sizes, int n_in,
                              void* d_out, int out_size)
{
    (void)in_sizes; (void)n_in; (void)out_size;
    const float* query     = (const float*)d_in[0];
    const float* key_value = (const float*)d_in[1];
    const float* fnorm_w   = (const float*)d_in[2];
    const float* cnorm_w   = (const float*)d_in[3];
    const float* f_Win     = (const float*)d_in[4];
    const float* f_convw   = (const float*)d_in[5];
    const float* f_convb   = (const float*)d_in[6];
    const float* f_dtbias  = (const float*)d_in[7];
    const float* f_Alog    = (const float*)d_in[8];
    const float* f_D       = (const float*)d_in[9];
    const float* f_normw   = (const float*)d_in[10];
    const float* f_Wout    = (const float*)d_in[11];
    const float* c_Win     = (const float*)d_in[12];
    const float* c_convw   = (const float*)d_in[13];
    const float* c_convb   = (const float*)d_in[14];
    const float* c_dtbias  = (const float*)d_in[15];
    const float* c_Alog    = (const float*)d_in[16];
    const float* c_D       = (const float*)d_in[17];
    const float* c_normw   = (const float*)d_in[18];
    const float* c_Wout    = (const float*)d_in[19];
    const float* outp_w    = (const float*)d_in[20];
    const float* outp_b    = (const float*)d_in[21];
    float* out = (float*)d_out;

    // 1) normalized input sequences (both blocks)
    k_build_u<<<dim3(LL, NB, NS), 128>>>(query, key_value, fnorm_w, cnorm_w);

    // 2) in_proj: Z = U @ Win_s   [8192 x 2192], K=512
    k_sgemm<<<dim3((DPJ + 127)/128, (NB*LL)/128, NS), 256>>>(
        f_Win, c_Win, nullptr, nullptr, 0, NB*LL, DPJ, DMO);

    // 3) causal dwconv + silu + dt/dA
    k_conv<<<dim3(LL, NB, NS), 128>>>(f_convw, c_convw, f_convb, c_convb,
                                      f_dtbias, c_dtbias, f_Alog, c_Alog);

    // 4-6) chunked SSD scan
    k_scanA<<<dim3(NC, NB*NH, NS), 64>>>();
    k_stateB<<<2048, 256>>>();
    k_scanC<<<dim3(NC, NB*NH, NS), 64>>>(f_D, c_D);

    // 7) gate + rmsnorm (in place in g_y)
    k_gatenorm<<<dim3(LL, NB, NS), 256>>>(f_normw, c_normw);

    // 8) Wout: fs = y_normed @ Wout_s   [8192 x 512], K=1024
    k_sgemm<<<dim3(512/128, (NB*LL)/128, NS), 256>>>(
        f_Wout, c_Wout, nullptr, nullptr, 1, NB*LL, DMO, DI);

    // 9) factual = fs_f[:,1024:] @ outp_w + outp_b  -> out[0 : 4096*512]
    k_sgemm<<<dim3(512/128, 4096/128, 1), 256>>>(
        outp_w, outp_w, outp_b, out, 2, 4096, DMO, DMO);

    // 10) counterfactual tail copy -> out[4096*512 : ]
    k_copycf<<<2048, 256>>>(out);
}

// round 5
// speedup vs baseline: 2.0910x; 2.0910x over previous
#include <cuda_runtime.h>
#include <math.h>
#include <stdint.h>

#define DINL __device__ __forceinline__

namespace {
constexpr int NS  = 2;      // 0 = factual, 1 = counterfactual
constexpr int NB  = 4;      // batch
constexpr int LKV = 1024;
constexpr int LL  = 2048;   // total seq len per block
constexpr int DMO = 512;    // d_model
constexpr int DPJ = 2192;   // d_in_proj
constexpr int DI  = 1024;   // d_inner
constexpr int DSZ = 64;     // d_state
constexpr int NH  = 16;
constexpr int HD  = 64;
constexpr int CC  = 1152;   // conv channels = DI + 2*DSZ
constexpr int CH  = 128;    // scan chunk length
constexpr int NC  = LL / CH;  // 16 chunks
constexpr int TS  = 8;      // time staging in scan kernels
}

// ---------------- scratch (device globals; no allocation) ----------------
__device__ float g_U  [(size_t)NS*NB*LL*DMO];          // rmsnorm'ed inputs
__device__ float g_Z  [(size_t)NS*NB*LL*DPJ];          // in_proj output
__device__ float g_xbc[(size_t)NS*NB*LL*CC];           // conv+silu output
__device__ float g_dt [(size_t)NS*NB*LL*NH];
__device__ float g_dA [(size_t)NS*NB*LL*NH];
__device__ float g_y  [(size_t)NS*NB*LL*DI];           // scan y -> gated/normed in place
__device__ float g_fs [(size_t)NS*NB*LL*DMO];          // per-block output (pre-final-proj)
__device__ float g_hloc  [(size_t)NS*NB*NH*NC*HD*DSZ]; // chunk-local end states
__device__ float g_hstart[(size_t)NS*NB*NH*NC*HD*DSZ]; // chunk start states
__device__ float g_P  [(size_t)NS*NB*NH*NC];           // per-chunk decay product

DINL float siluf(float x) { return x / (1.f + expf(-x)); }

DINL uint32_t f2tf(float f) {
    uint32_t u;
    asm("cvt.rna.tf32.f32 %0, %1;" : "=r"(u) : "f"(f));
    return u;
}

DINL void mma_tf32(float c[4], const uint32_t a[4], const uint32_t b[2]) {
    asm volatile(
        "mma.sync.aligned.m16n8k8.row.col.f32.tf32.tf32.f32 "
        "{%0,%1,%2,%3}, {%4,%5,%6,%7}, {%8,%9}, {%0,%1,%2,%3};"
        : "+f"(c[0]), "+f"(c[1]), "+f"(c[2]), "+f"(c[3])
        : "r"(a[0]), "r"(a[1]), "r"(a[2]), "r"(a[3]),
          "r"(b[0]), "r"(b[1]));
}

// ---------------- K1: build normalized input sequences -------------------
__global__ __launch_bounds__(128) void k_build_u(
    const float* __restrict__ q, const float* __restrict__ kv,
    const float* __restrict__ fw, const float* __restrict__ cw)
{
    int t = blockIdx.x, b = blockIdx.y, s = blockIdx.z;
    const float* src;
    if (t < LKV) {
        int tsrc = (s == 0) ? t : (LKV - 1 - t);   // counterfactual flips kv
        src = kv + ((size_t)b*LKV + tsrc)*DMO;
    } else {
        src = q + ((size_t)b*LKV + (t - LKV))*DMO;
    }
    const float* w = (s == 0) ? fw : cw;
    int tid = threadIdx.x;
    float4 v = ((const float4*)src)[tid];
    float ss = v.x*v.x + v.y*v.y + v.z*v.z + v.w*v.w;
    __shared__ float red[4];
    #pragma unroll
    for (int o = 16; o; o >>= 1) ss += __shfl_xor_sync(~0u, ss, o);
    if ((tid & 31) == 0) red[tid >> 5] = ss;
    __syncthreads();
    float tot = red[0] + red[1] + red[2] + red[3];
    float sc = rsqrtf(tot / (float)DMO + 1e-5f);
    float4 w4 = ((const float4*)w)[tid];
    float4 o4 = make_float4(v.x*sc*w4.x, v.y*sc*w4.y, v.z*sc*w4.z, v.w*sc*w4.w);
    ((float4*)(g_U + ((size_t)(s*NB + b)*LL + t)*DMO))[tid] = o4;
}

// ---- GEMM via TF32 mma.sync (128x128x16 tile, 8 warps of 64x32) ----------
// which: 0 => A=g_U,  C=g_Z   (per-s slices)
//        1 => A=g_y,  C=g_fs  (per-s slices)
//        2 => A=g_fs(s=0) row-remapped, C=Cext (+bias)
__global__ __launch_bounds__(256) void k_sgemm(
    const float* __restrict__ B0, const float* __restrict__ B1,
    const float* __restrict__ bias, float* __restrict__ Cext,
    int which, int M, int N, int K)
{
    constexpr int BMt = 128, BNt = 128, BKt = 16;
    constexpr int ASTR = BMt + 8;   // word stride; 136 % 32 = 8 -> conflict-free frag loads
    constexpr int BSTR = BNt + 8;
    int s = blockIdx.z;
    const float* Ap; float* Cp; int remapA = 0;
    if (which == 0) {
        Ap = g_U + (size_t)s*NB*LL*DMO;  Cp = g_Z + (size_t)s*NB*LL*DPJ;
    } else if (which == 1) {
        Ap = g_y + (size_t)s*NB*LL*DI;   Cp = g_fs + (size_t)s*NB*LL*DMO;
    } else {
        Ap = g_fs; Cp = Cext; remapA = 1;
    }
    const float* Bp = s ? B1 : B0;

    __shared__ uint32_t As[2][BKt][ASTR];   // tf32, [k][m]
    __shared__ uint32_t Bs[2][BKt][BSTR];   // tf32, [k][n]

    int tid  = threadIdx.x;
    int brow = blockIdx.y * BMt;
    int bcol = blockIdx.x * BNt;
    int warp = tid >> 5;
    int lane = tid & 31;
    int qr = lane >> 2, qc = lane & 3;
    int warp_m = (warp & 1) * 64;     // 2 warps over M
    int warp_n = (warp >> 1) * 32;    // 4 warps over N

    float c[4][4][4];                 // [tile_m][tile_n][frag]
    #pragma unroll
    for (int i = 0; i < 4; i++)
        #pragma unroll
        for (int j = 0; j < 4; j++)
            #pragma unroll
            for (int f = 0; f < 4; f++) c[i][j][f] = 0.f;

    int aRow = tid >> 2;          // 0..63
    int aCol = (tid & 3) << 2;    // 0,4,8,12
    int bRow = tid >> 5;          // 0..7
    int bCol = (tid & 31) << 2;   // 0..124

    // precompute global row/col indices (A-row remap for 'which==2')
    int growA[2];
    #pragma unroll
    for (int r = 0; r < 2; r++) {
        int gr = brow + aRow + r*64;
        if (remapA) gr = ((gr >> 10) << 11) + 1024 + (gr & 1023);
        growA[r] = gr;
    }
    int gcolB = bcol + bCol;
    bool bOK  = gcolB < N;

    // ---- prefetch tile 0 into registers, stage into buffer 0 ----
    float4 va[2], vb[2];
    #pragma unroll
    for (int r = 0; r < 2; r++)
        va[r] = *(const float4*)(Ap + (size_t)growA[r]*K + aCol);
    #pragma unroll
    for (int r = 0; r < 2; r++)
        vb[r] = bOK ? *(const float4*)(Bp + (size_t)(bRow + r*8)*N + gcolB)
                    : make_float4(0.f, 0.f, 0.f, 0.f);
    #pragma unroll
    for (int r = 0; r < 2; r++) {
        int row = aRow + r*64;
        As[0][aCol+0][row] = f2tf(va[r].x); As[0][aCol+1][row] = f2tf(va[r].y);
        As[0][aCol+2][row] = f2tf(va[r].z); As[0][aCol+3][row] = f2tf(va[r].w);
    }
    #pragma unroll
    for (int r = 0; r < 2; r++) {
        uint32_t* dst = &Bs[0][bRow + r*8][bCol];
        dst[0] = f2tf(vb[r].x); dst[1] = f2tf(vb[r].y);
        dst[2] = f2tf(vb[r].z); dst[3] = f2tf(vb[r].w);
    }
    __syncthreads();

    int buf = 0;
    for (int k0 = 0; k0 < K; k0 += BKt) {
        int kn = k0 + BKt;
        bool more = kn < K;

        // ---- issue prefetch of next tile (overlaps with MMA loop) ----
        if (more) {
            #pragma unroll
            for (int r = 0; r < 2; r++)
                va[r] = *(const float4*)(Ap + (size_t)growA[r]*K + kn + aCol);
            #pragma unroll
            for (int r = 0; r < 2; r++)
                vb[r] = bOK ? *(const float4*)(Bp + (size_t)(kn + bRow + r*8)*N + gcolB)
                            : make_float4(0.f, 0.f, 0.f, 0.f);
        }

        // ---- tensor-core MMAs over current tile (two k=8 steps) ----
        #pragma unroll
        for (int ks = 0; ks < 2; ks++) {
            int kk0 = ks*8;
            uint32_t af[4][4], bf[4][2];
            #pragma unroll
            for (int tm = 0; tm < 4; tm++) {
                int rb = warp_m + tm*16 + qr;
                af[tm][0] = As[buf][kk0 + qc    ][rb];
                af[tm][1] = As[buf][kk0 + qc    ][rb + 8];
                af[tm][2] = As[buf][kk0 + qc + 4][rb];
                af[tm][3] = As[buf][kk0 + qc + 4][rb + 8];
            }
            #pragma unroll
            for (int tn = 0; tn < 4; tn++) {
                int nb = warp_n + tn*8 + qr;
                bf[tn][0] = Bs[buf][kk0 + qc    ][nb];
                bf[tn][1] = Bs[buf][kk0 + qc + 4][nb];
            }
            #pragma unroll
            for (int tm = 0; tm < 4; tm++)
                #pragma unroll
                for (int tn = 0; tn < 4; tn++)
                    mma_tf32(c[tm][tn], af[tm], bf[tn]);
        }

        // ---- commit prefetched tile into the other buffer; single barrier ----
        if (more) {
            int nb = buf ^ 1;
            #pragma unroll
            for (int r = 0; r < 2; r++) {
                int row = aRow + r*64;
                As[nb][aCol+0][row] = f2tf(va[r].x); As[nb][aCol+1][row] = f2tf(va[r].y);
                As[nb][aCol+2][row] = f2tf(va[r].z); As[nb][aCol+3][row] = f2tf(va[r].w);
            }
            #pragma unroll
            for (int r = 0; r < 2; r++) {
                uint32_t* dst = &Bs[nb][bRow + r*8][bCol];
                dst[0] = f2tf(vb[r].x); dst[1] = f2tf(vb[r].y);
                dst[2] = f2tf(vb[r].z); dst[3] = f2tf(vb[r].w);
            }
            __syncthreads();
            buf = nb;
        }
    }

    // ---- epilogue: c frag (tm,tn): rows qr/(+8), cols 2*qc/(+1) ----
    #pragma unroll
    for (int tm = 0; tm < 4; tm++) {
        #pragma unroll
        for (int rh = 0; rh < 2; rh++) {
            int gr = brow + warp_m + tm*16 + qr + rh*8;
            #pragma unroll
            for (int tn = 0; tn < 4; tn++) {
                int gc = bcol + warp_n + tn*8 + 2*qc;
                if (gc < N) {
                    float2 o = make_float2(c[tm][tn][rh*2], c[tm][tn][rh*2 + 1]);
                    if (bias) { o.x += bias[gc]; o.y += bias[gc + 1]; }
                    *(float2*)(Cp + (size_t)gr*N + gc) = o;
                }
            }
        }
    }
}

// ---------------- K3: causal dwconv + silu + dt/dA ------------------------
__global__ __launch_bounds__(128) void k_conv(
    const float* __restrict__ cw0, const float* __restrict__ cw1,
    const float* __restrict__ cb0, const float* __restrict__ cb1,
    const float* __restrict__ db0, const float* __restrict__ db1,
    const float* __restrict__ al0, const float* __restrict__ al1)
{
    int t = blockIdx.x, b = blockIdx.y, s = blockIdx.z;
    const float* cw = s ? cw1 : cw0;
    const float* cb = s ? cb1 : cb0;
    const float* db = s ? db1 : db0;
    const float* al = s ? al1 : al0;
    size_t row = (size_t)(s*NB + b)*LL + t;

    #pragma unroll
    for (int it = 0; it < CC/128; it++) {
        int c = threadIdx.x + it*128;
        float acc = cb[c];
        #pragma unroll
        for (int k = 0; k < 4; k++) {
            int tt = t - 3 + k;
            if (tt >= 0)
                acc += g_Z[(row + (size_t)(tt - t))*DPJ + DI + c] * cw[c*4 + k];
        }
        g_xbc[row*CC + c] = siluf(acc);
    }
    if (threadIdx.x < NH) {
        int h = threadIdx.x;
        float v = g_Z[row*DPJ + 2*DI + 2*DSZ + h] + db[h];
        float dtv = (v > 20.f) ? v : log1pf(expf(v));
        g_dt[row*NH + h] = dtv;
        g_dA[row*NH + h] = expf(-expf(al[h]) * dtv);
    }
}

// ---------------- K4: intra-chunk scan (pass A) ---------------------------
__global__ __launch_bounds__(64) void k_scanA()
{
    int chunk = blockIdx.x;
    int b = blockIdx.y >> 4, h = blockIdx.y & 15;
    int s = blockIdx.z;
    int p = threadIdx.x;
    __shared__ float sB[TS][DSZ], sC[TS][DSZ], sX[TS][DSZ];
    __shared__ float sdA[TS], sdt[TS];

    float4 hreg[16];
    #pragma unroll
    for (int i = 0; i < 16; i++) hreg[i] = make_float4(0.f, 0.f, 0.f, 0.f);
    float Pprod = 1.f;

    size_t rowbase = (size_t)(s*NB + b)*LL + (size_t)chunk*CH;
    for (int t0 = 0; t0 < CH; t0 += TS) {
        __syncthreads();
        #pragma unroll
        for (int tt = 0; tt < TS; tt++) {
            const float* xb = g_xbc + (rowbase + t0 + tt)*CC;
            sB[tt][p] = xb[DI + p];
            sC[tt][p] = xb[DI + DSZ + p];
            sX[tt][p] = xb[h*HD + p];
        }
        if (p < TS) {
            size_t r = rowbase + t0 + p;
            sdA[p] = g_dA[r*NH + h];
            sdt[p] = g_dt[r*NH + h];
        }
        __syncthreads();
        #pragma unroll
        for (int tt = 0; tt < TS; tt++) {
            float dAt = sdA[tt];
            float scv = sdt[tt] * sX[tt][p];
            float y = 0.f;
            #pragma unroll
            for (int n4 = 0; n4 < 16; n4++) {
                float4 b4 = *(const float4*)&sB[tt][n4*4];
                float4 c4 = *(const float4*)&sC[tt][n4*4];
                hreg[n4].x = hreg[n4].x*dAt + scv*b4.x;  y += hreg[n4].x*c4.x;
                hreg[n4].y = hreg[n4].y*dAt + scv*b4.y;  y += hreg[n4].y*c4.y;
                hreg[n4].z = hreg[n4].z*dAt + scv*b4.z;  y += hreg[n4].z*c4.z;
                hreg[n4].w = hreg[n4].w*dAt + scv*b4.w;  y += hreg[n4].w*c4.w;
            }
            Pprod *= dAt;
            g_y[(rowbase + t0 + tt)*DI + h*HD + p] = y;
        }
    }
    size_t hidx = ((((size_t)(s*NB + b)*NH + h)*NC + chunk)*HD + p)*DSZ;
    #pragma unroll
    for (int n4 = 0; n4 < 16; n4++)
        *(float4*)(g_hloc + hidx + n4*4) = hreg[n4];
    if (p == 0) g_P[((size_t)(s*NB + b)*NH + h)*NC + chunk] = Pprod;
}

// ---------------- K5: inter-chunk state combine (pass B) ------------------
__global__ __launch_bounds__(256) void k_stateB()
{
    size_t idx = (size_t)blockIdx.x*256 + threadIdx.x; // over (sbh, p*n): 128*4096
    size_t sbh = idx >> 12;
    size_t pn  = idx & 4095;
    size_t base = sbh*(size_t)NC*4096 + pn;
    const float* Pv = g_P + sbh*NC;
    float hs = 0.f;
    #pragma unroll
    for (int c = 0; c < NC; c++) {
        g_hstart[base + (size_t)c*4096] = hs;
        hs = hs * Pv[c] + g_hloc[base + (size_t)c*4096];
    }
}

// ---------------- K6: inter-chunk correction + D*x (pass C) ---------------
__global__ __launch_bounds__(64) void k_scanC(
    const float* __restrict__ D0, const float* __restrict__ D1)
{
    int chunk = blockIdx.x;
    int b = blockIdx.y >> 4, h = blockIdx.y & 15;
    int s = blockIdx.z;
    int p = threadIdx.x;
    const float* Dv = s ? D1 : D0;
    float Dh = Dv[h];
    __shared__ float sC[TS][DSZ], sX[TS][DSZ];
    __shared__ float sdA[TS];

    float4 hs[16];
    size_t hidx = ((((size_t)(s*NB + b)*NH + h)*NC + chunk)*HD + p)*DSZ;
    #pragma unroll
    for (int n4 = 0; n4 < 16; n4++)
        hs[n4] = *(const float4*)(g_hstart + hidx + n4*4);

    float cum = 1.f;
    size_t rowbase = (size_t)(s*NB + b)*LL + (size_t)chunk*CH;
    for (int t0 = 0; t0 < CH; t0 += TS) {
        __syncthreads();
        #pragma unroll
        for (int tt = 0; tt < TS; tt++) {
            const float* xb = g_xbc + (rowbase + t0 + tt)*CC;
            sC[tt][p] = xb[DI + DSZ + p];
            sX[tt][p] = xb[h*HD + p];
        }
        if (p < TS) sdA[p] = g_dA[(rowbase + t0 + p)*NH + h];
        __syncthreads();
        #pragma unroll
        for (int tt = 0; tt < TS; tt++) {
            cum *= sdA[tt];
            float dot = 0.f;
            #pragma unroll
            for (int n4 = 0; n4 < 16; n4++) {
                float4 c4 = *(const float4*)&sC[tt][n4*4];
                dot += hs[n4].x*c4.x + hs[n4].y*c4.y + hs[n4].z*c4.z + hs[n4].w*c4.w;
            }
            size_t yi = (rowbase + t0 + tt)*DI + h*HD + p;
            g_y[yi] = g_y[yi] + cum*dot + Dh*sX[tt][p];
        }
    }
}

// ---------------- K7: gate (y * silu(z)) + rmsnorm, in place --------------
__global__ __launch_bounds__(256) void k_gatenorm(
    const float* __restrict__ nw0, const float* __restrict__ nw1)
{
    int t = blockIdx.x, b = blockIdx.y, s = blockIdx.z;
    const float* nw = s ? nw1 : nw0;
    size_t row = (size_t)(s*NB + b)*LL + t;
    int tid = threadIdx.x;
    float4 y4 = ((const float4*)(g_y + row*DI))[tid];
    float4 z4 = ((const float4*)(g_Z + row*DPJ))[tid];
    z4.x = siluf(z4.x); z4.y = siluf(z4.y); z4.z = siluf(z4.z); z4.w = siluf(z4.w);
    float4 yz = make_float4(y4.x*z4.x, y4.y*z4.y, y4.z*z4.z, y4.w*z4.w);
    float ss = yz.x*yz.x + yz.y*yz.y + yz.z*yz.z + yz.w*yz.w;
    __shared__ float red[8];
    #pragma unroll
    for (int o = 16; o; o >>= 1) ss += __shfl_xor_sync(~0u, ss, o);
    if ((tid & 31) == 0) red[tid >> 5] = ss;
    __syncthreads();
    float tot = 0.f;
    #pragma unroll
    for (int i = 0; i < 8; i++) tot += red[i];
    float sc = rsqrtf(tot / (float)DI + 1e-5f);
    float4 w4 = ((const float4*)nw)[tid];
    ((float4*)(g_y + row*DI))[tid] =
        make_float4(yz.x*sc*w4.x, yz.y*sc*w4.y, yz.z*sc*w4.z, yz.w*sc*w4.w);
}

// ---------------- K9: copy counterfactual tail to output ------------------
__global__ __launch_bounds__(256) void k_copycf(float* __restrict__ out)
{
    size_t i = (size_t)blockIdx.x*256 + threadIdx.x;   // float4 idx over 4096*512/4
    size_t r  = i >> 7;          // 0..4095
    size_t c4 = i & 127;
    size_t srcrow = ((r >> 10) << 11) + 1024 + (r & 1023);
    float4 v = ((const float4*)(g_fs + (size_t)NB*LL*DMO + srcrow*DMO))[c4];
    ((float4*)(out + (size_t)4096*512))[i] = v;
}

// ---------------- launch ---------------------------------------------------
extern "C" void kernel_launch(void* const* d_in, const int* in_sizes, int n_in,
                              void* d_out, int out_size)
{
    (void)in_sizes; (void)n_in; (void)out_size;
    const float* query     = (const float*)d_in[0];
    const float* key_value = (const float*)d_in[1];
    const float* fnorm_w   = (const float*)d_in[2];
    const float* cnorm_w   = (const float*)d_in[3];
    const float* f_Win     = (const float*)d_in[4];
    const float* f_convw   = (const float*)d_in[5];
    const float* f_convb   = (const float*)d_in[6];
    const float* f_dtbias  = (const float*)d_in[7];
    const float* f_Alog    = (const float*)d_in[8];
    const float* f_D       = (const float*)d_in[9];
    const float* f_normw   = (const float*)d_in[10];
    const float* f_Wout    = (const float*)d_in[11];
    const float* c_Win     = (const float*)d_in[12];
    const float* c_convw   = (const float*)d_in[13];
    const float* c_convb   = (const float*)d_in[14];
    const float* c_dtbias  = (const float*)d_in[15];
    const float* c_Alog    = (const float*)d_in[16];
    const float* c_D       = (const float*)d_in[17];
    const float* c_normw   = (const float*)d_in[18];
    const float* c_Wout    = (const float*)d_in[19];
    const float* outp_w    = (const float*)d_in[20];
    const float* outp_b    = (const float*)d_in[21];
    float* out = (float*)d_out;

    // 1) normalized input sequences (both blocks)
    k_build_u<<<dim3(LL, NB, NS), 128>>>(query, key_value, fnorm_w, cnorm_w);

    // 2) in_proj: Z = U @ Win_s   [8192 x 2192], K=512
    k_sgemm<<<dim3((DPJ + 127)/128, (NB*LL)/128, NS), 256>>>(
        f_Win, c_Win, nullptr, nullptr, 0, NB*LL, DPJ, DMO);

    // 3) causal dwconv + silu + dt/dA
    k_conv<<<dim3(LL, NB, NS), 128>>>(f_convw, c_convw, f_convb, c_convb,
                                      f_dtbias, c_dtbias, f_Alog, c_Alog);

    // 4-6) chunked SSD scan
    k_scanA<<<dim3(NC, NB*NH, NS), 64>>>();
    k_stateB<<<2048, 256>>>();
    k_scanC<<<dim3(NC, NB*NH, NS), 64>>>(f_D, c_D);

    // 7) gate + rmsnorm (in place in g_y)
    k_gatenorm<<<dim3(LL, NB, NS), 256>>>(f_normw, c_normw);

    // 8) Wout: fs = y_normed @ Wout_s   [8192 x 512], K=1024
    k_sgemm<<<dim3(512/128, (NB*LL)/128, NS), 256>>>(
        f_Wout, c_Wout, nullptr, nullptr, 1, NB*LL, DMO, DI);

    // 9) factual = fs_f[:,1024:] @ outp_w + outp_b  -> out[0 : 4096*512]
    k_sgemm<<<dim3(512/128, 4096/128, 1), 256>>>(
        outp_w, outp_w, outp_b, out, 2, 4096, DMO, DMO);

    // 10) counterfactual tail copy -> out[4096*512 : ]
    k_copycf<<<2048, 256>>>(out);
}

// round 7
// speedup vs baseline: 2.1484x; 1.0274x over previous
#include <cuda_runtime.h>
#include <math.h>
#include <stdint.h>

#define DINL __device__ __forceinline__

namespace {
constexpr int NS  = 2;      // 0 = factual, 1 = counterfactual
constexpr int NB  = 4;      // batch
constexpr int LKV = 1024;
constexpr int LL  = 2048;   // total seq len per block
constexpr int DMO = 512;    // d_model
constexpr int DPJ = 2192;   // d_in_proj
constexpr int DI  = 1024;   // d_inner
constexpr int DSZ = 64;     // d_state
constexpr int NH  = 16;
constexpr int HD  = 64;
constexpr int CC  = 1152;   // conv channels = DI + 2*DSZ
constexpr int CH  = 128;    // scan chunk length
constexpr int NC  = LL / CH;  // 16 chunks
constexpr int TS  = 8;      // time staging in scan kernels
}

// ---------------- scratch (device globals; no allocation) ----------------
__device__ float g_U  [(size_t)NS*NB*LL*DMO];          // rmsnorm'ed inputs
__device__ float g_Z  [(size_t)NS*NB*LL*DPJ];          // in_proj output
__device__ float g_xbc[(size_t)NS*NB*LL*CC];           // conv+silu output
__device__ float g_dt [(size_t)NS*NB*LL*NH];
__device__ float g_dA [(size_t)NS*NB*LL*NH];
__device__ float g_y  [(size_t)NS*NB*LL*DI];           // scan y -> gated/normed in place
__device__ float g_fs [(size_t)NS*NB*LL*DMO];          // per-block output (pre-final-proj)
__device__ float g_hloc  [(size_t)NS*NB*NH*NC*HD*DSZ]; // chunk-local end states
__device__ float g_hstart[(size_t)NS*NB*NH*NC*HD*DSZ]; // chunk start states
__device__ float g_P  [(size_t)NS*NB*NH*NC];           // per-chunk decay product

DINL float siluf(float x) { return x / (1.f + expf(-x)); }

DINL uint32_t f2tf(float f) {
    uint32_t u;
    asm("cvt.rna.tf32.f32 %0, %1;" : "=r"(u) : "f"(f));
    return u;
}

DINL void mma_tf32(float c[4], const uint32_t a[4], const uint32_t b[2]) {
    asm volatile(
        "mma.sync.aligned.m16n8k8.row.col.f32.tf32.tf32.f32 "
        "{%0,%1,%2,%3}, {%4,%5,%6,%7}, {%8,%9}, {%0,%1,%2,%3};"
        : "+f"(c[0]), "+f"(c[1]), "+f"(c[2]), "+f"(c[3])
        : "r"(a[0]), "r"(a[1]), "r"(a[2]), "r"(a[3]),
          "r"(b[0]), "r"(b[1]));
}

// ---- packed fp32x2 helpers (Blackwell FFMA2 path; PTX-only) --------------
typedef unsigned long long u64t;

DINL u64t pk2(float lo, float hi) {
    u64t r;
    asm("mov.b64 %0, {%1, %2};" : "=l"(r) : "f"(lo), "f"(hi));
    return r;
}
DINL void upk2(float& lo, float& hi, u64t v) {
    asm("mov.b64 {%0, %1}, %2;" : "=f"(lo), "=f"(hi) : "l"(v));
}
DINL u64t mul2(u64t a, u64t b) {
    u64t d;
    asm("mul.rn.f32x2 %0, %1, %2;" : "=l"(d) : "l"(a), "l"(b));
    return d;
}
DINL u64t fma2(u64t a, u64t b, u64t c) {
    u64t d;
    asm("fma.rn.f32x2 %0, %1, %2, %3;" : "=l"(d) : "l"(a), "l"(b), "l"(c));
    return d;
}

// ---------------- K1: build normalized input sequences -------------------
__global__ __launch_bounds__(128) void k_build_u(
    const float* __restrict__ q, const float* __restrict__ kv,
    const float* __restrict__ fw, const float* __restrict__ cw)
{
    int t = blockIdx.x, b = blockIdx.y, s = blockIdx.z;
    const float* src;
    if (t < LKV) {
        int tsrc = (s == 0) ? t : (LKV - 1 - t);   // counterfactual flips kv
        src = kv + ((size_t)b*LKV + tsrc)*DMO;
    } else {
        src = q + ((size_t)b*LKV + (t - LKV))*DMO;
    }
    const float* w = (s == 0) ? fw : cw;
    int tid = threadIdx.x;
    float4 v = ((const float4*)src)[tid];
    float ss = v.x*v.x + v.y*v.y + v.z*v.z + v.w*v.w;
    __shared__ float red[4];
    #pragma unroll
    for (int o = 16; o; o >>= 1) ss += __shfl_xor_sync(~0u, ss, o);
    if ((tid & 31) == 0) red[tid >> 5] = ss;
    __syncthreads();
    float tot = red[0] + red[1] + red[2] + red[3];
    float sc = rsqrtf(tot / (float)DMO + 1e-5f);
    float4 w4 = ((const float4*)w)[tid];
    float4 o4 = make_float4(v.x*sc*w4.x, v.y*sc*w4.y, v.z*sc*w4.z, v.w*sc*w4.w);
    ((float4*)(g_U + ((size_t)(s*NB + b)*LL + t)*DMO))[tid] = o4;
}

// ---- GEMM via TF32 mma.sync (128x128x16 tile, 8 warps of 64x32) ----------
// which: 0 => A=g_U,  C=g_Z   (per-s slices)
//        1 => A=g_y,  C=g_fs  (per-s slices)
//        2 => A=g_fs(s=0) row-remapped, C=Cext (+bias)
__global__ __launch_bounds__(256) void k_sgemm(
    const float* __restrict__ B0, const float* __restrict__ B1,
    const float* __restrict__ bias, float* __restrict__ Cext,
    int which, int M, int N, int K)
{
    constexpr int BMt = 128, BNt = 128, BKt = 16;
    constexpr int ASTR = BMt + 8;   // word stride; 136 % 32 = 8 -> conflict-free frag loads
    constexpr int BSTR = BNt + 8;
    int s = blockIdx.z;
    const float* Ap; float* Cp; int remapA = 0;
    if (which == 0) {
        Ap = g_U + (size_t)s*NB*LL*DMO;  Cp = g_Z + (size_t)s*NB*LL*DPJ;
    } else if (which == 1) {
        Ap = g_y + (size_t)s*NB*LL*DI;   Cp = g_fs + (size_t)s*NB*LL*DMO;
    } else {
        Ap = g_fs; Cp = Cext; remapA = 1;
    }
    const float* Bp = s ? B1 : B0;

    __shared__ uint32_t As[2][BKt][ASTR];   // tf32, [k][m]
    __shared__ uint32_t Bs[2][BKt][BSTR];   // tf32, [k][n]

    int tid  = threadIdx.x;
    int brow = blockIdx.y * BMt;
    int bcol = blockIdx.x * BNt;
    int warp = tid >> 5;
    int lane = tid & 31;
    int qr = lane >> 2, qc = lane & 3;
    int warp_m = (warp & 1) * 64;     // 2 warps over M
    int warp_n = (warp >> 1) * 32;    // 4 warps over N

    float c[4][4][4];                 // [tile_m][tile_n][frag]
    #pragma unroll
    for (int i = 0; i < 4; i++)
        #pragma unroll
        for (int j = 0; j < 4; j++)
            #pragma unroll
            for (int f = 0; f < 4; f++) c[i][j][f] = 0.f;

    int aRow = tid >> 2;          // 0..63
    int aCol = (tid & 3) << 2;    // 0,4,8,12
    int bRow = tid >> 5;          // 0..7
    int bCol = (tid & 31) << 2;   // 0..124

    // precompute global row/col indices (A-row remap for 'which==2')
    int growA[2];
    #pragma unroll
    for (int r = 0; r < 2; r++) {
        int gr = brow + aRow + r*64;
        if (remapA) gr = ((gr >> 10) << 11) + 1024 + (gr & 1023);
        growA[r] = gr;
    }
    int gcolB = bcol + bCol;
    bool bOK  = gcolB < N;

    // ---- prefetch tile 0 into registers, stage into buffer 0 ----
    float4 va[2], vb[2];
    #pragma unroll
    for (int r = 0; r < 2; r++)
        va[r] = *(const float4*)(Ap + (size_t)growA[r]*K + aCol);
    #pragma unroll
    for (int r = 0; r < 2; r++)
        vb[r] = bOK ? *(const float4*)(Bp + (size_t)(bRow + r*8)*N + gcolB)
                    : make_float4(0.f, 0.f, 0.f, 0.f);
    #pragma unroll
    for (int r = 0; r < 2; r++) {
        int row = aRow + r*64;
        As[0][aCol+0][row] = f2tf(va[r].x); As[0][aCol+1][row] = f2tf(va[r].y);
        As[0][aCol+2][row] = f2tf(va[r].z); As[0][aCol+3][row] = f2tf(va[r].w);
    }
    #pragma unroll
    for (int r = 0; r < 2; r++) {
        uint32_t* dst = &Bs[0][bRow + r*8][bCol];
        dst[0] = f2tf(vb[r].x); dst[1] = f2tf(vb[r].y);
        dst[2] = f2tf(vb[r].z); dst[3] = f2tf(vb[r].w);
    }
    __syncthreads();

    int buf = 0;
    for (int k0 = 0; k0 < K; k0 += BKt) {
        int kn = k0 + BKt;
        bool more = kn < K;

        // ---- issue prefetch of next tile (overlaps with MMA loop) ----
        if (more) {
            #pragma unroll
            for (int r = 0; r < 2; r++)
                va[r] = *(const float4*)(Ap + (size_t)growA[r]*K + kn + aCol);
            #pragma unroll
            for (int r = 0; r < 2; r++)
                vb[r] = bOK ? *(const float4*)(Bp + (size_t)(kn + bRow + r*8)*N + gcolB)
                            : make_float4(0.f, 0.f, 0.f, 0.f);
        }

        // ---- tensor-core MMAs over current tile (two k=8 steps) ----
        #pragma unroll
        for (int ks = 0; ks < 2; ks++) {
            int kk0 = ks*8;
            uint32_t af[4][4], bf[4][2];
            #pragma unroll
            for (int tm = 0; tm < 4; tm++) {
                int rb = warp_m + tm*16 + qr;
                af[tm][0] = As[buf][kk0 + qc    ][rb];
                af[tm][1] = As[buf][kk0 + qc    ][rb + 8];
                af[tm][2] = As[buf][kk0 + qc + 4][rb];
                af[tm][3] = As[buf][kk0 + qc + 4][rb + 8];
            }
            #pragma unroll
            for (int tn = 0; tn < 4; tn++) {
                int nb = warp_n + tn*8 + qr;
                bf[tn][0] = Bs[buf][kk0 + qc    ][nb];
                bf[tn][1] = Bs[buf][kk0 + qc + 4][nb];
            }
            #pragma unroll
            for (int tm = 0; tm < 4; tm++)
                #pragma unroll
                for (int tn = 0; tn < 4; tn++)
                    mma_tf32(c[tm][tn], af[tm], bf[tn]);
        }

        // ---- commit prefetched tile into the other buffer; single barrier ----
        if (more) {
            int nb = buf ^ 1;
            #pragma unroll
            for (int r = 0; r < 2; r++) {
                int row = aRow + r*64;
                As[nb][aCol+0][row] = f2tf(va[r].x); As[nb][aCol+1][row] = f2tf(va[r].y);
                As[nb][aCol+2][row] = f2tf(va[r].z); As[nb][aCol+3][row] = f2tf(va[r].w);
            }
            #pragma unroll
            for (int r = 0; r < 2; r++) {
                uint32_t* dst = &Bs[nb][bRow + r*8][bCol];
                dst[0] = f2tf(vb[r].x); dst[1] = f2tf(vb[r].y);
                dst[2] = f2tf(vb[r].z); dst[3] = f2tf(vb[r].w);
            }
            __syncthreads();
            buf = nb;
        }
    }

    // ---- epilogue: c frag (tm,tn): rows qr/(+8), cols 2*qc/(+1) ----
    #pragma unroll
    for (int tm = 0; tm < 4; tm++) {
        #pragma unroll
        for (int rh = 0; rh < 2; rh++) {
            int gr = brow + warp_m + tm*16 + qr + rh*8;
            #pragma unroll
            for (int tn = 0; tn < 4; tn++) {
                int gc = bcol + warp_n + tn*8 + 2*qc;
                if (gc < N) {
                    float2 o = make_float2(c[tm][tn][rh*2], c[tm][tn][rh*2 + 1]);
                    if (bias) { o.x += bias[gc]; o.y += bias[gc + 1]; }
                    *(float2*)(Cp + (size_t)gr*N + gc) = o;
                }
            }
        }
    }
}

// ---------------- K3: causal dwconv + silu + dt/dA ------------------------
__global__ __launch_bounds__(128) void k_conv(
    const float* __restrict__ cw0, const float* __restrict__ cw1,
    const float* __restrict__ cb0, const float* __restrict__ cb1,
    const float* __restrict__ db0, const float* __restrict__ db1,
    const float* __restrict__ al0, const float* __restrict__ al1)
{
    int t = blockIdx.x, b = blockIdx.y, s = blockIdx.z;
    const float* cw = s ? cw1 : cw0;
    const float* cb = s ? cb1 : cb0;
    const float* db = s ? db1 : db0;
    const float* al = s ? al1 : al0;
    size_t row = (size_t)(s*NB + b)*LL + t;

    #pragma unroll
    for (int it = 0; it < CC/128; it++) {
        int c = threadIdx.x + it*128;
        float acc = cb[c];
        #pragma unroll
        for (int k = 0; k < 4; k++) {
            int tt = t - 3 + k;
            if (tt >= 0)
                acc += g_Z[(row + (size_t)(tt - t))*DPJ + DI + c] * cw[c*4 + k];
        }
        g_xbc[row*CC + c] = siluf(acc);
    }
    if (threadIdx.x < NH) {
        int h = threadIdx.x;
        float v = g_Z[row*DPJ + 2*DI + 2*DSZ + h] + db[h];
        float dtv = (v > 20.f) ? v : log1pf(expf(v));
        g_dt[row*NH + h] = dtv;
        g_dA[row*NH + h] = expf(-expf(al[h]) * dtv);
    }
}

// ---------------- K4: intra-chunk scan (pass A, packed f32x2) -------------
__global__ __launch_bounds__(64) void k_scanA()
{
    int chunk = blockIdx.x;
    int b = blockIdx.y >> 4, h = blockIdx.y & 15;
    int s = blockIdx.z;
    int p = threadIdx.x;
    __shared__ __align__(16) float sB[TS][DSZ];
    __shared__ __align__(16) float sC[TS][DSZ];
    __shared__ __align__(16) float sX[TS][DSZ];
    __shared__ float sdA[TS], sdt[TS];

    u64t h2[32];                      // 64 fp32 states as 32 packed pairs
    #pragma unroll
    for (int i = 0; i < 32; i++) h2[i] = 0ull;
    float Pprod = 1.f;

    size_t rowbase = (size_t)(s*NB + b)*LL + (size_t)chunk*CH;
    for (int t0 = 0; t0 < CH; t0 += TS) {
        __syncthreads();
        #pragma unroll
        for (int tt = 0; tt < TS; tt++) {
            const float* xb = g_xbc + (rowbase + t0 + tt)*CC;
            sB[tt][p] = xb[DI + p];
            sC[tt][p] = xb[DI + DSZ + p];
            sX[tt][p] = xb[h*HD + p];
        }
        if (p < TS) {
            size_t r = rowbase + t0 + p;
            sdA[p] = g_dA[r*NH + h];
            sdt[p] = g_dt[r*NH + h];
        }
        __syncthreads();
        #pragma unroll
        for (int tt = 0; tt < TS; tt++) {
            float dAt = sdA[tt];
            float scv = sdt[tt] * sX[tt][p];
            u64t dA2  = pk2(dAt, dAt);
            u64t scv2 = pk2(scv, scv);
            u64t ya = 0ull, yb = 0ull;   // two accumulators break the chain
            const u64t* b64 = (const u64t*)&sB[tt][0];
            const u64t* c64 = (const u64t*)&sC[tt][0];
            #pragma unroll
            for (int n2 = 0; n2 < 32; n2 += 2) {
                u64t t0v = mul2(scv2, b64[n2]);
                h2[n2] = fma2(h2[n2], dA2, t0v);
                ya = fma2(h2[n2], c64[n2], ya);
                u64t t1v = mul2(scv2, b64[n2+1]);
                h2[n2+1] = fma2(h2[n2+1], dA2, t1v);
                yb = fma2(h2[n2+1], c64[n2+1], yb);
            }
            Pprod *= dAt;
            float l0, h0, l1, h1;
            upk2(l0, h0, ya); upk2(l1, h1, yb);
            g_y[(rowbase + t0 + tt)*DI + h*HD + p] = (l0 + h0) + (l1 + h1);
        }
    }
    size_t hidx = ((((size_t)(s*NB + b)*NH + h)*NC + chunk)*HD + p)*DSZ;
    u64t* hout = (u64t*)(g_hloc + hidx);
    #pragma unroll
    for (int n2 = 0; n2 < 32; n2++) hout[n2] = h2[n2];
    if (p == 0) g_P[((size_t)(s*NB + b)*NH + h)*NC + chunk] = Pprod;
}

// ---------------- K5: inter-chunk state combine (pass B) ------------------
__global__ __launch_bounds__(256) void k_stateB()
{
    size_t idx = (size_t)blockIdx.x*256 + threadIdx.x; // over (sbh, p*n): 128*4096
    size_t sbh = idx >> 12;
    size_t pn  = idx & 4095;
    size_t base = sbh*(size_t)NC*4096 + pn;
    const float* Pv = g_P + sbh*NC;
    float hs = 0.f;
    #pragma unroll
    for (int c = 0; c < NC; c++) {
        g_hstart[base + (size_t)c*4096] = hs;
        hs = hs * Pv[c] + g_hloc[base + (size_t)c*4096];
    }
}

// ---------------- K6: inter-chunk correction + D*x (pass C, packed) -------
__global__ __launch_bounds__(64) void k_scanC(
    const float* __restrict__ D0, const float* __restrict__ D1)
{
    int chunk = blockIdx.x;
    int b = blockIdx.y >> 4, h = blockIdx.y & 15;
    int s = blockIdx.z;
    int p = threadIdx.x;
    const float* Dv = s ? D1 : D0;
    float Dh = Dv[h];
    __shared__ __align__(16) float sC[TS][DSZ];
    __shared__ __align__(16) float sX[TS][DSZ];
    __shared__ float sdA[TS];

    u64t hs2[32];
    size_t hidx = ((((size_t)(s*NB + b)*NH + h)*NC + chunk)*HD + p)*DSZ;
    const u64t* hin = (const u64t*)(g_hstart + hidx);
    #pragma unroll
    for (int n2 = 0; n2 < 32; n2++) hs2[n2] = hin[n2];

    float cum = 1.f;
    size_t rowbase = (size_t)(s*NB + b)*LL + (size_t)chunk*CH;
    for (int t0 = 0; t0 < CH; t0 += TS) {
        __syncthreads();
        #pragma unroll
        for (int tt = 0; tt < TS; tt++) {
            const float* xb = g_xbc + (rowbase + t0 + tt)*CC;
            sC[tt][p] = xb[DI + DSZ + p];
            sX[tt][p] = xb[h*HD + p];
        }
        if (p < TS) sdA[p] = g_dA[(rowbase + t0 + p)*NH + h];
        __syncthreads();
        #pragma unroll
        for (int tt = 0; tt < TS; tt++) {
            cum *= sdA[tt];
            u64t da = 0ull, db = 0ull;
            const u64t* c64 = (const u64t*)&sC[tt][0];
            #pragma unroll
            for (int n2 = 0; n2 < 32; n2 += 2) {
                da = fma2(hs2[n2],   c64[n2],   da);
                db = fma2(hs2[n2+1], c64[n2+1], db);
            }
            float l0, h0, l1, h1;
            upk2(l0, h0, da); upk2(l1, h1, db);
            float dot = (l0 + h0) + (l1 + h1);
            size_t yi = (rowbase + t0 + tt)*DI + h*HD + p;
            g_y[yi] = g_y[yi] + cum*dot + Dh*sX[tt][p];
        }
    }
}

// ---------------- K7: gate (y * silu(z)) + rmsnorm, in place --------------
__global__ __launch_bounds__(256) void k_gatenorm(
    const float* __restrict__ nw0, const float* __restrict__ nw1)
{
    int t = blockIdx.x, b = blockIdx.y, s = blockIdx.z;
    const float* nw = s ? nw1 : nw0;
    size_t row = (size_t)(s*NB + b)*LL + t;
    int tid = threadIdx.x;
    float4 y4 = ((const float4*)(g_y + row*DI))[tid];
    float4 z4 = ((const float4*)(g_Z + row*DPJ))[tid];
    z4.x = siluf(z4.x); z4.y = siluf(z4.y); z4.z = siluf(z4.z); z4.w = siluf(z4.w);
    float4 yz = make_float4(y4.x*z4.x, y4.y*z4.y, y4.z*z4.z, y4.w*z4.w);
    float ss = yz.x*yz.x + yz.y*yz.y + yz.z*yz.z + yz.w*yz.w;
    __shared__ float red[8];
    #pragma unroll
    for (int o = 16; o; o >>= 1) ss += __shfl_xor_sync(~0u, ss, o);
    if ((tid & 31) == 0) red[tid >> 5] = ss;
    __syncthreads();
    float tot = 0.f;
    #pragma unroll
    for (int i = 0; i < 8; i++) tot += red[i];
    float sc = rsqrtf(tot / (float)DI + 1e-5f);
    float4 w4 = ((const float4*)nw)[tid];
    ((float4*)(g_y + row*DI))[tid] =
        make_float4(yz.x*sc*w4.x, yz.y*sc*w4.y, yz.z*sc*w4.z, yz.w*sc*w4.w);
}

// ---------------- K9: copy counterfactual tail to output ------------------
__global__ __launch_bounds__(256) void k_copycf(float* __restrict__ out)
{
    size_t i = (size_t)blockIdx.x*256 + threadIdx.x;   // float4 idx over 4096*512/4
    size_t r  = i >> 7;          // 0..4095
    size_t c4 = i & 127;
    size_t srcrow = ((r >> 10) << 11) + 1024 + (r & 1023);
    float4 v = ((const float4*)(g_fs + (size_t)NB*LL*DMO + srcrow*DMO))[c4];
    ((float4*)(out + (size_t)4096*512))[i] = v;
}

// ---------------- launch ---------------------------------------------------
extern "C" void kernel_launch(void* const* d_in, const int* in_sizes, int n_in,
                              void* d_out, int out_size)
{
    (void)in_sizes; (void)n_in; (void)out_size;
    const float* query     = (const float*)d_in[0];
    const float* key_value = (const float*)d_in[1];
    const float* fnorm_w   = (const float*)d_in[2];
    const float* cnorm_w   = (const float*)d_in[3];
    const float* f_Win     = (const float*)d_in[4];
    const float* f_convw   = (const float*)d_in[5];
    const float* f_convb   = (const float*)d_in[6];
    const float* f_dtbias  = (const float*)d_in[7];
    const float* f_Alog    = (const float*)d_in[8];
    const float* f_D       = (const float*)d_in[9];
    const float* f_normw   = (const float*)d_in[10];
    const float* f_Wout    = (const float*)d_in[11];
    const float* c_Win     = (const float*)d_in[12];
    const float* c_convw   = (const float*)d_in[13];
    const float* c_convb   = (const float*)d_in[14];
    const float* c_dtbias  = (const float*)d_in[15];
    const float* c_Alog    = (const float*)d_in[16];
    const float* c_D       = (const float*)d_in[17];
    const float* c_normw   = (const float*)d_in[18];
    const float* c_Wout    = (const float*)d_in[19];
    const float* outp_w    = (const float*)d_in[20];
    const float* outp_b    = (const float*)d_in[21];
    float* out = (float*)d_out;

    // 1) normalized input sequences (both blocks)
    k_build_u<<<dim3(LL, NB, NS), 128>>>(query, key_value, fnorm_w, cnorm_w);

    // 2) in_proj: Z = U @ Win_s   [8192 x 2192], K=512
    k_sgemm<<<dim3((DPJ + 127)/128, (NB*LL)/128, NS), 256>>>(
        f_Win, c_Win, nullptr, nullptr, 0, NB*LL, DPJ, DMO);

    // 3) causal dwconv + silu + dt/dA
    k_conv<<<dim3(LL, NB, NS), 128>>>(f_convw, c_convw, f_convb, c_convb,
                                      f_dtbias, c_dtbias, f_Alog, c_Alog);

    // 4-6) chunked SSD scan
    k_scanA<<<dim3(NC, NB*NH, NS), 64>>>();
    k_stateB<<<2048, 256>>>();
    k_scanC<<<dim3(NC, NB*NH, NS), 64>>>(f_D, c_D);

    // 7) gate + rmsnorm (in place in g_y)
    k_gatenorm<<<dim3(LL, NB, NS), 256>>>(f_normw, c_normw);

    // 8) Wout: fs = y_normed @ Wout_s   [8192 x 512], K=1024
    k_sgemm<<<dim3(512/128, (NB*LL)/128, NS), 256>>>(
        f_Wout, c_Wout, nullptr, nullptr, 1, NB*LL, DMO, DI);

    // 9) factual = fs_f[:,1024:] @ outp_w + outp_b  -> out[0 : 4096*512]
    k_sgemm<<<dim3(512/128, 4096/128, 1), 256>>>(
        outp_w, outp_w, outp_b, out, 2, 4096, DMO, DMO);

    // 10) counterfactual tail copy -> out[4096*512 : ]
    k_copycf<<<2048, 256>>>(out);
}

// round 9
// speedup vs baseline: 2.1556x; 1.0034x over previous
#include <cuda_runtime.h>
#include <math.h>
#include <stdint.h>

#define DINL __device__ __forceinline__

namespace {
constexpr int NS  = 2;      // 0 = factual, 1 = counterfactual
constexpr int NB  = 4;      // batch
constexpr int LKV = 1024;
constexpr int LL  = 2048;   // total seq len per block
constexpr int DMO = 512;    // d_model
constexpr int DPJ = 2192;   // d_in_proj
constexpr int DI  = 1024;   // d_inner
constexpr int DSZ = 64;     // d_state
constexpr int NH  = 16;
constexpr int HD  = 64;
constexpr int CC  = 1152;   // conv channels = DI + 2*DSZ
constexpr int CH  = 128;    // scan chunk length
constexpr int NC  = LL / CH;  // 16 chunks
constexpr int TS  = 8;      // time staging in scan kernels
}

// ---------------- scratch (device globals; no allocation) ----------------
__device__ float g_U  [(size_t)NS*NB*LL*DMO];          // rmsnorm'ed inputs
__device__ float g_Z  [(size_t)NS*NB*LL*DPJ];          // in_proj output
__device__ float g_xbc[(size_t)NS*NB*LL*CC];           // conv+silu output
__device__ float g_dt [(size_t)NS*NB*LL*NH];
__device__ float g_dA [(size_t)NS*NB*LL*NH];
__device__ float g_y  [(size_t)NS*NB*LL*DI];           // scan y -> gated/normed in place
__device__ float g_fs [(size_t)NS*NB*LL*DMO];          // per-block output (pre-final-proj)
__device__ float g_hloc  [(size_t)NS*NB*NH*NC*HD*DSZ]; // chunk-local end states
__device__ float g_hstart[(size_t)NS*NB*NH*NC*HD*DSZ]; // chunk start states
__device__ float g_P  [(size_t)NS*NB*NH*NC];           // per-chunk decay product

DINL float siluf(float x) { return x / (1.f + expf(-x)); }

DINL uint32_t f2tf(float f) {
    uint32_t u;
    asm("cvt.rna.tf32.f32 %0, %1;" : "=r"(u) : "f"(f));
    return u;
}

DINL void mma_tf32(float c[4], const uint32_t a[4], const uint32_t b[2]) {
    asm volatile(
        "mma.sync.aligned.m16n8k8.row.col.f32.tf32.tf32.f32 "
        "{%0,%1,%2,%3}, {%4,%5,%6,%7}, {%8,%9}, {%0,%1,%2,%3};"
        : "+f"(c[0]), "+f"(c[1]), "+f"(c[2]), "+f"(c[3])
        : "r"(a[0]), "r"(a[1]), "r"(a[2]), "r"(a[3]),
          "r"(b[0]), "r"(b[1]));
}

// ---- packed fp32x2 helpers (Blackwell FFMA2 path; PTX-only) --------------
typedef unsigned long long u64t;

DINL u64t pk2(float lo, float hi) {
    u64t r;
    asm("mov.b64 %0, {%1, %2};" : "=l"(r) : "f"(lo), "f"(hi));
    return r;
}
DINL void upk2(float& lo, float& hi, u64t v) {
    asm("mov.b64 {%0, %1}, %2;" : "=f"(lo), "=f"(hi) : "l"(v));
}
DINL u64t mul2(u64t a, u64t b) {
    u64t d;
    asm("mul.rn.f32x2 %0, %1, %2;" : "=l"(d) : "l"(a), "l"(b));
    return d;
}
DINL u64t fma2(u64t a, u64t b, u64t c) {
    u64t d;
    asm("fma.rn.f32x2 %0, %1, %2, %3;" : "=l"(d) : "l"(a), "l"(b), "l"(c));
    return d;
}

// ---------------- K1: build normalized input sequences -------------------
__global__ __launch_bounds__(128) void k_build_u(
    const float* __restrict__ q, const float* __restrict__ kv,
    const float* __restrict__ fw, const float* __restrict__ cw)
{
    int t = blockIdx.x, b = blockIdx.y, s = blockIdx.z;
    const float* src;
    if (t < LKV) {
        int tsrc = (s == 0) ? t : (LKV - 1 - t);   // counterfactual flips kv
        src = kv + ((size_t)b*LKV + tsrc)*DMO;
    } else {
        src = q + ((size_t)b*LKV + (t - LKV))*DMO;
    }
    const float* w = (s == 0) ? fw : cw;
    int tid = threadIdx.x;
    float4 v = ((const float4*)src)[tid];
    float ss = v.x*v.x + v.y*v.y + v.z*v.z + v.w*v.w;
    __shared__ float red[4];
    #pragma unroll
    for (int o = 16; o; o >>= 1) ss += __shfl_xor_sync(~0u, ss, o);
    if ((tid & 31) == 0) red[tid >> 5] = ss;
    __syncthreads();
    float tot = red[0] + red[1] + red[2] + red[3];
    float sc = rsqrtf(tot / (float)DMO + 1e-5f);
    float4 w4 = ((const float4*)w)[tid];
    float4 o4 = make_float4(v.x*sc*w4.x, v.y*sc*w4.y, v.z*sc*w4.z, v.w*sc*w4.w);
    ((float4*)(g_U + ((size_t)(s*NB + b)*LL + t)*DMO))[tid] = o4;
}

// ---- GEMM via TF32 mma.sync (128x128x16 tile, 8 warps of 64x32) ----------
// which: 0 => A=g_U,  C=g_Z   (per-s slices)
//        1 => A=g_y,  C=g_fs  (per-s slices)
//        2 => A=g_fs(s=0) row-remapped, C=Cext (+bias)
__global__ __launch_bounds__(256) void k_sgemm(
    const float* __restrict__ B0, const float* __restrict__ B1,
    const float* __restrict__ bias, float* __restrict__ Cext,
    int which, int M, int N, int K)
{
    constexpr int BMt = 128, BNt = 128, BKt = 16;
    constexpr int ASTR = BMt + 8;   // word stride; 136 % 32 = 8 -> conflict-free frag loads
    constexpr int BSTR = BNt + 8;
    int s = blockIdx.z;
    const float* Ap; float* Cp; int remapA = 0;
    if (which == 0) {
        Ap = g_U + (size_t)s*NB*LL*DMO;  Cp = g_Z + (size_t)s*NB*LL*DPJ;
    } else if (which == 1) {
        Ap = g_y + (size_t)s*NB*LL*DI;   Cp = g_fs + (size_t)s*NB*LL*DMO;
    } else {
        Ap = g_fs; Cp = Cext; remapA = 1;
    }
    const float* Bp = s ? B1 : B0;

    __shared__ uint32_t As[2][BKt][ASTR];   // tf32, [k][m]
    __shared__ uint32_t Bs[2][BKt][BSTR];   // tf32, [k][n]

    int tid  = threadIdx.x;
    int brow = blockIdx.y * BMt;
    int bcol = blockIdx.x * BNt;
    int warp = tid >> 5;
    int lane = tid & 31;
    int qr = lane >> 2, qc = lane & 3;
    int warp_m = (warp & 1) * 64;     // 2 warps over M
    int warp_n = (warp >> 1) * 32;    // 4 warps over N

    float c[4][4][4];                 // [tile_m][tile_n][frag]
    #pragma unroll
    for (int i = 0; i < 4; i++)
        #pragma unroll
        for (int j = 0; j < 4; j++)
            #pragma unroll
            for (int f = 0; f < 4; f++) c[i][j][f] = 0.f;

    int aRow = tid >> 2;          // 0..63
    int aCol = (tid & 3) << 2;    // 0,4,8,12
    int bRow = tid >> 5;          // 0..7
    int bCol = (tid & 31) << 2;   // 0..124

    // precompute global row/col indices (A-row remap for 'which==2')
    int growA[2];
    #pragma unroll
    for (int r = 0; r < 2; r++) {
        int gr = brow + aRow + r*64;
        if (remapA) gr = ((gr >> 10) << 11) + 1024 + (gr & 1023);
        growA[r] = gr;
    }
    int gcolB = bcol + bCol;
    bool bOK  = gcolB < N;

    // ---- prefetch tile 0 into registers, stage into buffer 0 ----
    float4 va[2], vb[2];
    #pragma unroll
    for (int r = 0; r < 2; r++)
        va[r] = *(const float4*)(Ap + (size_t)growA[r]*K + aCol);
    #pragma unroll
    for (int r = 0; r < 2; r++)
        vb[r] = bOK ? *(const float4*)(Bp + (size_t)(bRow + r*8)*N + gcolB)
                    : make_float4(0.f, 0.f, 0.f, 0.f);
    #pragma unroll
    for (int r = 0; r < 2; r++) {
        int row = aRow + r*64;
        As[0][aCol+0][row] = f2tf(va[r].x); As[0][aCol+1][row] = f2tf(va[r].y);
        As[0][aCol+2][row] = f2tf(va[r].z); As[0][aCol+3][row] = f2tf(va[r].w);
    }
    #pragma unroll
    for (int r = 0; r < 2; r++) {
        uint32_t* dst = &Bs[0][bRow + r*8][bCol];
        dst[0] = f2tf(vb[r].x); dst[1] = f2tf(vb[r].y);
        dst[2] = f2tf(vb[r].z); dst[3] = f2tf(vb[r].w);
    }
    __syncthreads();

    int buf = 0;
    for (int k0 = 0; k0 < K; k0 += BKt) {
        int kn = k0 + BKt;
        bool more = kn < K;

        // ---- issue prefetch of next tile (overlaps with MMA loop) ----
        if (more) {
            #pragma unroll
            for (int r = 0; r < 2; r++)
                va[r] = *(const float4*)(Ap + (size_t)growA[r]*K + kn + aCol);
            #pragma unroll
            for (int r = 0; r < 2; r++)
                vb[r] = bOK ? *(const float4*)(Bp + (size_t)(kn + bRow + r*8)*N + gcolB)
                            : make_float4(0.f, 0.f, 0.f, 0.f);
        }

        // ---- tensor-core MMAs over current tile (two k=8 steps) ----
        #pragma unroll
        for (int ks = 0; ks < 2; ks++) {
            int kk0 = ks*8;
            uint32_t af[4][4], bf[4][2];
            #pragma unroll
            for (int tm = 0; tm < 4; tm++) {
                int rb = warp_m + tm*16 + qr;
                af[tm][0] = As[buf][kk0 + qc    ][rb];
                af[tm][1] = As[buf][kk0 + qc    ][rb + 8];
                af[tm][2] = As[buf][kk0 + qc + 4][rb];
                af[tm][3] = As[buf][kk0 + qc + 4][rb + 8];
            }
            #pragma unroll
            for (int tn = 0; tn < 4; tn++) {
                int nb = warp_n + tn*8 + qr;
                bf[tn][0] = Bs[buf][kk0 + qc    ][nb];
                bf[tn][1] = Bs[buf][kk0 + qc + 4][nb];
            }
            #pragma unroll
            for (int tm = 0; tm < 4; tm++)
                #pragma unroll
                for (int tn = 0; tn < 4; tn++)
                    mma_tf32(c[tm][tn], af[tm], bf[tn]);
        }

        // ---- commit prefetched tile into the other buffer; single barrier ----
        if (more) {
            int nb = buf ^ 1;
            #pragma unroll
            for (int r = 0; r < 2; r++) {
                int row = aRow + r*64;
                As[nb][aCol+0][row] = f2tf(va[r].x); As[nb][aCol+1][row] = f2tf(va[r].y);
                As[nb][aCol+2][row] = f2tf(va[r].z); As[nb][aCol+3][row] = f2tf(va[r].w);
            }
            #pragma unroll
            for (int r = 0; r < 2; r++) {
                uint32_t* dst = &Bs[nb][bRow + r*8][bCol];
                dst[0] = f2tf(vb[r].x); dst[1] = f2tf(vb[r].y);
                dst[2] = f2tf(vb[r].z); dst[3] = f2tf(vb[r].w);
            }
            __syncthreads();
            buf = nb;
        }
    }

    // ---- epilogue: c frag (tm,tn): rows qr/(+8), cols 2*qc/(+1) ----
    #pragma unroll
    for (int tm = 0; tm < 4; tm++) {
        #pragma unroll
        for (int rh = 0; rh < 2; rh++) {
            int gr = brow + warp_m + tm*16 + qr + rh*8;
            #pragma unroll
            for (int tn = 0; tn < 4; tn++) {
                int gc = bcol + warp_n + tn*8 + 2*qc;
                if (gc < N) {
                    float2 o = make_float2(c[tm][tn][rh*2], c[tm][tn][rh*2 + 1]);
                    if (bias) { o.x += bias[gc]; o.y += bias[gc + 1]; }
                    *(float2*)(Cp + (size_t)gr*N + gc) = o;
                }
            }
        }
    }
}

// ---------------- K3: causal dwconv + silu + dt/dA ------------------------
__global__ __launch_bounds__(128) void k_conv(
    const float* __restrict__ cw0, const float* __restrict__ cw1,
    const float* __restrict__ cb0, const float* __restrict__ cb1,
    const float* __restrict__ db0, const float* __restrict__ db1,
    const float* __restrict__ al0, const float* __restrict__ al1)
{
    int t = blockIdx.x, b = blockIdx.y, s = blockIdx.z;
    const float* cw = s ? cw1 : cw0;
    const float* cb = s ? cb1 : cb0;
    const float* db = s ? db1 : db0;
    const float* al = s ? al1 : al0;
    size_t row = (size_t)(s*NB + b)*LL + t;

    #pragma unroll
    for (int it = 0; it < CC/128; it++) {
        int c = threadIdx.x + it*128;
        float acc = cb[c];
        #pragma unroll
        for (int k = 0; k < 4; k++) {
            int tt = t - 3 + k;
            if (tt >= 0)
                acc += g_Z[(row + (size_t)(tt - t))*DPJ + DI + c] * cw[c*4 + k];
        }
        g_xbc[row*CC + c] = siluf(acc);
    }
    if (threadIdx.x < NH) {
        int h = threadIdx.x;
        float v = g_Z[row*DPJ + 2*DI + 2*DSZ + h] + db[h];
        float dtv = (v > 20.f) ? v : log1pf(expf(v));
        g_dt[row*NH + h] = dtv;
        g_dA[row*NH + h] = expf(-expf(al[h]) * dtv);
    }
}

// ---------------- K4: intra-chunk scan (pass A, packed + LDS.128) ---------
__global__ __launch_bounds__(64) void k_scanA()
{
    int chunk = blockIdx.x;
    int b = blockIdx.y >> 4, h = blockIdx.y & 15;
    int s = blockIdx.z;
    int p = threadIdx.x;
    __shared__ __align__(16) float sB[TS][DSZ];
    __shared__ __align__(16) float sC[TS][DSZ];
    __shared__ __align__(16) float sX[TS][DSZ];
    __shared__ float sdA[TS], sdt[TS];

    u64t h2[32];                      // 64 fp32 states as 32 packed pairs
    #pragma unroll
    for (int i = 0; i < 32; i++) h2[i] = 0ull;
    float Pprod = 1.f;

    size_t rowbase = (size_t)(s*NB + b)*LL + (size_t)chunk*CH;
    for (int t0 = 0; t0 < CH; t0 += TS) {
        __syncthreads();
        // vectorized staging: 2 float4 per array per thread covers 8x64 floats
        #pragma unroll
        for (int r = 0; r < 2; r++) {
            int it = p + r*64;           // 0..127
            int tt = it >> 4;            // 8 rows
            int c4 = (it & 15) << 2;     // 16 float4 per row
            const float* xb = g_xbc + (rowbase + t0 + tt)*CC;
            *(float4*)&sB[tt][c4] = *(const float4*)(xb + DI + c4);
            *(float4*)&sC[tt][c4] = *(const float4*)(xb + DI + DSZ + c4);
            *(float4*)&sX[tt][c4] = *(const float4*)(xb + h*HD + c4);
        }
        if (p < TS) {
            size_t r = rowbase + t0 + p;
            sdA[p] = g_dA[r*NH + h];
            sdt[p] = g_dt[r*NH + h];
        }
        __syncthreads();
        #pragma unroll
        for (int tt = 0; tt < TS; tt++) {
            float dAt = sdA[tt];
            float scv = sdt[tt] * sX[tt][p];
            u64t dA2  = pk2(dAt, dAt);
            u64t scv2 = pk2(scv, scv);
            u64t ya = 0ull, yb = 0ull;   // two accumulators break the chain
            const ulonglong2* b2 = (const ulonglong2*)&sB[tt][0];
            const ulonglong2* c2 = (const ulonglong2*)&sC[tt][0];
            #pragma unroll
            for (int n4 = 0; n4 < 16; n4++) {
                ulonglong2 bb = b2[n4];
                ulonglong2 cc = c2[n4];
                h2[2*n4]   = fma2(h2[2*n4],   dA2, mul2(scv2, bb.x));
                ya = fma2(h2[2*n4],   cc.x, ya);
                h2[2*n4+1] = fma2(h2[2*n4+1], dA2, mul2(scv2, bb.y));
                yb = fma2(h2[2*n4+1], cc.y, yb);
            }
            Pprod *= dAt;
            float l0, h0, l1, h1;
            upk2(l0, h0, ya); upk2(l1, h1, yb);
            g_y[(rowbase + t0 + tt)*DI + h*HD + p] = (l0 + h0) + (l1 + h1);
        }
    }
    size_t hidx = ((((size_t)(s*NB + b)*NH + h)*NC + chunk)*HD + p)*DSZ;
    ulonglong2* hout = (ulonglong2*)(g_hloc + hidx);
    #pragma unroll
    for (int n4 = 0; n4 < 16; n4++) {
        ulonglong2 v; v.x = h2[2*n4]; v.y = h2[2*n4+1];
        hout[n4] = v;
    }
    if (p == 0) g_P[((size_t)(s*NB + b)*NH + h)*NC + chunk] = Pprod;
}

// ---------------- K5: inter-chunk state combine (pass B) ------------------
__global__ __launch_bounds__(256) void k_stateB()
{
    size_t idx = (size_t)blockIdx.x*256 + threadIdx.x; // over (sbh, p*n): 128*4096
    size_t sbh = idx >> 12;
    size_t pn  = idx & 4095;
    size_t base = sbh*(size_t)NC*4096 + pn;
    const float* Pv = g_P + sbh*NC;
    float hs = 0.f;
    #pragma unroll
    for (int c = 0; c < NC; c++) {
        g_hstart[base + (size_t)c*4096] = hs;
        hs = hs * Pv[c] + g_hloc[base + (size_t)c*4096];
    }
}

// ---------------- K6: inter-chunk correction + D*x (packed + LDS.128) -----
__global__ __launch_bounds__(64) void k_scanC(
    const float* __restrict__ D0, const float* __restrict__ D1)
{
    int chunk = blockIdx.x;
    int b = blockIdx.y >> 4, h = blockIdx.y & 15;
    int s = blockIdx.z;
    int p = threadIdx.x;
    const float* Dv = s ? D1 : D0;
    float Dh = Dv[h];
    __shared__ __align__(16) float sC[TS][DSZ];
    __shared__ __align__(16) float sX[TS][DSZ];
    __shared__ float sdA[TS];

    u64t hs2[32];
    size_t hidx = ((((size_t)(s*NB + b)*NH + h)*NC + chunk)*HD + p)*DSZ;
    const ulonglong2* hin = (const ulonglong2*)(g_hstart + hidx);
    #pragma unroll
    for (int n4 = 0; n4 < 16; n4++) {
        ulonglong2 v = hin[n4];
        hs2[2*n4] = v.x; hs2[2*n4+1] = v.y;
    }

    float cum = 1.f;
    size_t rowbase = (size_t)(s*NB + b)*LL + (size_t)chunk*CH;
    for (int t0 = 0; t0 < CH; t0 += TS) {
        __syncthreads();
        #pragma unroll
        for (int r = 0; r < 2; r++) {
            int it = p + r*64;
            int tt = it >> 4;
            int c4 = (it & 15) << 2;
            const float* xb = g_xbc + (rowbase + t0 + tt)*CC;
            *(float4*)&sC[tt][c4] = *(const float4*)(xb + DI + DSZ + c4);
            *(float4*)&sX[tt][c4] = *(const float4*)(xb + h*HD + c4);
        }
        if (p < TS) sdA[p] = g_dA[(rowbase + t0 + p)*NH + h];
        __syncthreads();
        #pragma unroll
        for (int tt = 0; tt < TS; tt++) {
            cum *= sdA[tt];
            u64t da = 0ull, db = 0ull;
            const ulonglong2* c2 = (const ulonglong2*)&sC[tt][0];
            #pragma unroll
            for (int n4 = 0; n4 < 16; n4++) {
                ulonglong2 cc = c2[n4];
                da = fma2(hs2[2*n4],   cc.x, da);
                db = fma2(hs2[2*n4+1], cc.y, db);
            }
            float l0, h0, l1, h1;
            upk2(l0, h0, da); upk2(l1, h1, db);
            float dot = (l0 + h0) + (l1 + h1);
            size_t yi = (rowbase + t0 + tt)*DI + h*HD + p;
            g_y[yi] = g_y[yi] + cum*dot + Dh*sX[tt][p];
        }
    }
}

// ---------------- K7: gate (y * silu(z)) + rmsnorm, in place --------------
__global__ __launch_bounds__(256) void k_gatenorm(
    const float* __restrict__ nw0, const float* __restrict__ nw1)
{
    int t = blockIdx.x, b = blockIdx.y, s = blockIdx.z;
    const float* nw = s ? nw1 : nw0;
    size_t row = (size_t)(s*NB + b)*LL + t;
    int tid = threadIdx.x;
    float4 y4 = ((const float4*)(g_y + row*DI))[tid];
    float4 z4 = ((const float4*)(g_Z + row*DPJ))[tid];
    z4.x = siluf(z4.x); z4.y = siluf(z4.y); z4.z = siluf(z4.z); z4.w = siluf(z4.w);
    float4 yz = make_float4(y4.x*z4.x, y4.y*z4.y, y4.z*z4.z, y4.w*z4.w);
    float ss = yz.x*yz.x + yz.y*yz.y + yz.z*yz.z + yz.w*yz.w;
    __shared__ float red[8];
    #pragma unroll
    for (int o = 16; o; o >>= 1) ss += __shfl_xor_sync(~0u, ss, o);
    if ((tid & 31) == 0) red[tid >> 5] = ss;
    __syncthreads();
    float tot = 0.f;
    #pragma unroll
    for (int i = 0; i < 8; i++) tot += red[i];
    float sc = rsqrtf(tot / (float)DI + 1e-5f);
    float4 w4 = ((const float4*)nw)[tid];
    ((float4*)(g_y + row*DI))[tid] =
        make_float4(yz.x*sc*w4.x, yz.y*sc*w4.y, yz.z*sc*w4.z, yz.w*sc*w4.w);
}

// ---------------- K9: copy counterfactual tail to output ------------------
__global__ __launch_bounds__(256) void k_copycf(float* __restrict__ out)
{
    size_t i = (size_t)blockIdx.x*256 + threadIdx.x;   // float4 idx over 4096*512/4
    size_t r  = i >> 7;          // 0..4095
    size_t c4 = i & 127;
    size_t srcrow = ((r >> 10) << 11) + 1024 + (r & 1023);
    float4 v = ((const float4*)(g_fs + (size_t)NB*LL*DMO + srcrow*DMO))[c4];
    ((float4*)(out + (size_t)4096*512))[i] = v;
}

// ---------------- launch ---------------------------------------------------
extern "C" void kernel_launch(void* const* d_in, const int* in_sizes, int n_in,
                              void* d_out, int out_size)
{
    (void)in_sizes; (void)n_in; (void)out_size;
    const float* query     = (const float*)d_in[0];
    const float* key_value = (const float*)d_in[1];
    const float* fnorm_w   = (const float*)d_in[2];
    const float* cnorm_w   = (const float*)d_in[3];
    const float* f_Win     = (const float*)d_in[4];
    const float* f_convw   = (const float*)d_in[5];
    const float* f_convb   = (const float*)d_in[6];
    const float* f_dtbias  = (const float*)d_in[7];
    const float* f_Alog    = (const float*)d_in[8];
    const float* f_D       = (const float*)d_in[9];
    const float* f_normw   = (const float*)d_in[10];
    const float* f_Wout    = (const float*)d_in[11];
    const float* c_Win     = (const float*)d_in[12];
    const float* c_convw   = (const float*)d_in[13];
    const float* c_convb   = (const float*)d_in[14];
    const float* c_dtbias  = (const float*)d_in[15];
    const float* c_Alog    = (const float*)d_in[16];
    const float* c_D       = (const float*)d_in[17];
    const float* c_normw   = (const float*)d_in[18];
    const float* c_Wout    = (const float*)d_in[19];
    const float* outp_w    = (const float*)d_in[20];
    const float* outp_b    = (const float*)d_in[21];
    float* out = (float*)d_out;

    // 1) normalized input sequences (both blocks)
    k_build_u<<<dim3(LL, NB, NS), 128>>>(query, key_value, fnorm_w, cnorm_w);

    // 2) in_proj: Z = U @ Win_s   [8192 x 2192], K=512
    k_sgemm<<<dim3((DPJ + 127)/128, (NB*LL)/128, NS), 256>>>(
        f_Win, c_Win, nullptr, nullptr, 0, NB*LL, DPJ, DMO);

    // 3) causal dwconv + silu + dt/dA
    k_conv<<<dim3(LL, NB, NS), 128>>>(f_convw, c_convw, f_convb, c_convb,
                                      f_dtbias, c_dtbias, f_Alog, c_Alog);

    // 4-6) chunked SSD scan
    k_scanA<<<dim3(NC, NB*NH, NS), 64>>>();
    k_stateB<<<2048, 256>>>();
    k_scanC<<<dim3(NC, NB*NH, NS), 64>>>(f_D, c_D);

    // 7) gate + rmsnorm (in place in g_y)
    k_gatenorm<<<dim3(LL, NB, NS), 256>>>(f_normw, c_normw);

    // 8) Wout: fs = y_normed @ Wout_s   [8192 x 512], K=1024
    k_sgemm<<<dim3(512/128, (NB*LL)/128, NS), 256>>>(
        f_Wout, c_Wout, nullptr, nullptr, 1, NB*LL, DMO, DI);

    // 9) factual = fs_f[:,1024:] @ outp_w + outp_b  -> out[0 : 4096*512]
    k_sgemm<<<dim3(512/128, 4096/128, 1), 256>>>(
        outp_w, outp_w, outp_b, out, 2, 4096, DMO, DMO);

    // 10) counterfactual tail copy -> out[4096*512 : ]
    k_copycf<<<2048, 256>>>(out);
}